// round 6
// baseline (speedup 1.0000x reference)
#include <cuda_runtime.h>
#include <cuda_fp16.h>
#include <math.h>
#include <stdint.h>

#define SS 2048
#define RR 512
#define NT 256

// ---- shared memory layout (32-bit word offsets) ----
static constexpr int OFF_WGF  = 0;                    // Wg B-frags 2048
static constexpr int OFF_WOF  = 2048;                 // Wo B-frags 2048
static constexpr int OFF_WKF  = 4096;                 // Wk frags 256
static constexpr int OFF_WVF  = 4352;                 // Wv frags 256
static constexpr int OFF_KV   = 4608;                 // 512 rows * 9: K(4xh2) V(4xh2) bias(f32)
static constexpr int OFF_MASK = OFF_KV + RR * 9;      // 512
static constexpr int OFF_PART = OFF_MASK + 512;       // 8 warps * 64
static constexpr int OFF_POOL = OFF_PART + 512;       // 64 (unnormalized)
static constexpr int OFF_QH   = OFF_POOL + 64;        // 64
static constexpr int OFF_OF   = OFF_QH + 64;          // 64
static constexpr int OFF_BG   = OFF_OF + 64;          // 64
static constexpr int OFF_BO   = OFF_BG + 64;          // 64
static constexpr int SMEM_WORDS = OFF_BO + 64;        // 10560
static constexpr int SMEM_BYTES = SMEM_WORDS * 4;     // 42240 B

__device__ __forceinline__ uint32_t packh2(float lo, float hi) {
    __half2 h = __floats2half2_rn(lo, hi);
    return *(uint32_t*)&h;
}
__device__ __forceinline__ float2 h2f2(uint32_t u) {
    return __half22float2(*(__half2*)&u);
}
__device__ __forceinline__ void mma_f16(float c[4], const uint32_t a[4],
                                        uint32_t b0, uint32_t b1)
{
    asm("mma.sync.aligned.m16n8k16.row.col.f32.f16.f16.f32 "
        "{%0,%1,%2,%3}, {%4,%5,%6,%7}, {%8,%9}, {%0,%1,%2,%3};"
        : "+f"(c[0]), "+f"(c[1]), "+f"(c[2]), "+f"(c[3])
        : "r"(a[0]), "r"(a[1]), "r"(a[2]), "r"(a[3]), "r"(b0), "r"(b1));
}

__global__ void __launch_bounds__(NT, 2) ga_kernel(
    const float* __restrict__ m, const float* __restrict__ mask,
    const float* __restrict__ Wq, const float* __restrict__ Wk,
    const float* __restrict__ Wv, const float* __restrict__ Wg,
    const float* __restrict__ bg, const float* __restrict__ Wo,
    const float* __restrict__ bo, float* __restrict__ out)
{
    extern __shared__ float sm[];
    uint32_t* smu = (uint32_t*)sm;
    const int s    = blockIdx.x;
    const int tid  = threadIdx.x;
    const int warp = tid >> 5, lane = tid & 31;
    const int qrow = lane >> 2, qcol = lane & 3;
    const float* m_s    = m + (size_t)s * (RR * 64);
    const float* mask_g = mask + (size_t)s * RR;

    // ---------- Phase 0: weight frags + mask + KV bias (no m staging!) ----------
    {
        // B-fragments (m16n8k16.row.col): b0={W[k0][n],W[k0+1][n]}, b1={W[k0+8][n],W[k0+9][n]},
        // k0 = ktg*16 + 2*qcol, n = nt*8 + qrow
        #pragma unroll
        for (int it = 0; it < 4; ++it) {
            int idx = it * 8 + warp;          // 0..31 -> (nt, ktg)
            int nt = idx >> 2, ktg = idx & 3;
            int d0 = ktg * 16 + 2 * qcol;
            int cc = nt * 8 + qrow;
            int off = ((nt * 4 + ktg) * 32 + lane) * 2;
            smu[OFF_WGF + off]     = packh2(Wg[d0 * 64 + cc],       Wg[(d0 + 1) * 64 + cc]);
            smu[OFF_WGF + off + 1] = packh2(Wg[(d0 + 8) * 64 + cc], Wg[(d0 + 9) * 64 + cc]);
            smu[OFF_WOF + off]     = packh2(Wo[d0 * 64 + cc],       Wo[(d0 + 1) * 64 + cc]);
            smu[OFF_WOF + off + 1] = packh2(Wo[(d0 + 8) * 64 + cc], Wo[(d0 + 9) * 64 + cc]);
        }
        if (warp < 4) {
            int ktg = warp;
            int d0 = ktg * 16 + 2 * qcol;
            int off = (ktg * 32 + lane) * 2;
            smu[OFF_WKF + off]     = packh2(Wk[d0 * 8 + qrow],       Wk[(d0 + 1) * 8 + qrow]);
            smu[OFF_WKF + off + 1] = packh2(Wk[(d0 + 8) * 8 + qrow], Wk[(d0 + 9) * 8 + qrow]);
            smu[OFF_WVF + off]     = packh2(Wv[d0 * 8 + qrow],       Wv[(d0 + 1) * 8 + qrow]);
            smu[OFF_WVF + off + 1] = packh2(Wv[(d0 + 8) * 8 + qrow], Wv[(d0 + 9) * 8 + qrow]);
        }
        #pragma unroll
        for (int i = tid; i < RR; i += NT) {
            float mk = __ldg(mask_g + i);
            sm[OFF_MASK + i] = mk;
            sm[OFF_KV + i * 9 + 8] = 1e9f * (mk - 1.0f);   // softmax bias
        }
        if (tid < 64) { sm[OFF_BG + tid] = bg[tid]; sm[OFF_BO + tid] = bo[tid]; }
    }
    __syncthreads();   // B1

    // ================= each warp owns 64 rows r0..r0+63 =================
    const int r0 = warp * 64;

    // ---------- Phase 1: k/v GEMM from gmem A-frags, pool partials folded in ----------
    {
        float mk0[4], mk1[4];
        #pragma unroll
        for (int mt = 0; mt < 4; ++mt) {
            mk0[mt] = sm[OFF_MASK + r0 + mt * 16 + qrow];
            mk1[mt] = sm[OFF_MASK + r0 + mt * 16 + qrow + 8];
        }
        float2 pc[4][2];
        #pragma unroll
        for (int k = 0; k < 4; ++k) { pc[k][0] = make_float2(0.f, 0.f); pc[k][1] = make_float2(0.f, 0.f); }

        float ck[4][4] = {{0,0,0,0},{0,0,0,0},{0,0,0,0},{0,0,0,0}};
        float cv[4][4] = {{0,0,0,0},{0,0,0,0},{0,0,0,0},{0,0,0,0}};

        #pragma unroll
        for (int ktg = 0; ktg < 4; ++ktg) {
            uint32_t A[4][4];
            #pragma unroll
            for (int mt = 0; mt < 4; ++mt) {
                const float* base = m_s + (r0 + mt * 16 + qrow) * 64 + ktg * 16 + 2 * qcol;
                float2 f0 = *(const float2*)base;            // (row,   k..k+1)
                float2 f1 = *(const float2*)(base + 8 * 64); // (row+8, k..k+1)
                float2 f2 = *(const float2*)(base + 8);      // (row,   k+8..k+9)
                float2 f3 = *(const float2*)(base + 8 * 64 + 8);
                A[mt][0] = packh2(f0.x, f0.y);
                A[mt][1] = packh2(f1.x, f1.y);
                A[mt][2] = packh2(f2.x, f2.y);
                A[mt][3] = packh2(f3.x, f3.y);
                pc[ktg][0].x += f0.x * mk0[mt] + f1.x * mk1[mt];
                pc[ktg][0].y += f0.y * mk0[mt] + f1.y * mk1[mt];
                pc[ktg][1].x += f2.x * mk0[mt] + f3.x * mk1[mt];
                pc[ktg][1].y += f2.y * mk0[mt] + f3.y * mk1[mt];
            }
            uint32_t bk0 = smu[OFF_WKF + (ktg * 32 + lane) * 2];
            uint32_t bk1 = smu[OFF_WKF + (ktg * 32 + lane) * 2 + 1];
            uint32_t bv0 = smu[OFF_WVF + (ktg * 32 + lane) * 2];
            uint32_t bv1 = smu[OFF_WVF + (ktg * 32 + lane) * 2 + 1];
            #pragma unroll
            for (int mt = 0; mt < 4; ++mt) {
                mma_f16(ck[mt], A[mt], bk0, bk1);
                mma_f16(cv[mt], A[mt], bv0, bv1);
            }
        }
        // KV store (fp16 interleaved, stride 9 words)
        #pragma unroll
        for (int mt = 0; mt < 4; ++mt) {
            int row = r0 + mt * 16 + qrow;
            smu[OFF_KV + row * 9 + qcol]           = packh2(ck[mt][0], ck[mt][1]);
            smu[OFF_KV + (row + 8) * 9 + qcol]     = packh2(ck[mt][2], ck[mt][3]);
            smu[OFF_KV + row * 9 + 4 + qcol]       = packh2(cv[mt][0], cv[mt][1]);
            smu[OFF_KV + (row + 8) * 9 + 4 + qcol] = packh2(cv[mt][2], cv[mt][3]);
        }
        // pool partial reduce over qrow (lanes sharing qcol): xor 4, 8, 16
        #pragma unroll
        for (int k = 0; k < 4; ++k)
            #pragma unroll
            for (int p = 0; p < 2; ++p) {
                #pragma unroll
                for (int o = 4; o <= 16; o <<= 1) {
                    pc[k][p].x += __shfl_xor_sync(0xFFFFFFFFu, pc[k][p].x, o);
                    pc[k][p].y += __shfl_xor_sync(0xFFFFFFFFu, pc[k][p].y, o);
                }
            }
        if (lane < 4) {   // qrow == 0
            #pragma unroll
            for (int k = 0; k < 4; ++k) {
                *(float2*)&sm[OFF_PART + warp * 64 + k * 16 + 2 * qcol]     = pc[k][0];
                *(float2*)&sm[OFF_PART + warp * 64 + k * 16 + 8 + 2 * qcol] = pc[k][1];
            }
        }
    }
    __syncthreads();   // B2: KV + PART ready

    // ---------- Phase 2: q per warp (redundant pool; benign duplicate POOL write) ----------
    float qv[8];
    {
        float p0 = 0.f, p1 = 0.f;
        #pragma unroll
        for (int w = 0; w < 8; ++w) {
            p0 += sm[OFF_PART + w * 64 + lane];
            p1 += sm[OFF_PART + w * 64 + lane + 32];
        }
        sm[OFF_POOL + lane]      = p0;   // all warps write identical values
        sm[OFF_POOL + lane + 32] = p1;
        float ms = 0.f;
        #pragma unroll
        for (int j = 0; j < 16; ++j) ms += sm[OFF_MASK + lane + 32 * j];
        #pragma unroll
        for (int o = 16; o; o >>= 1) ms += __shfl_xor_sync(0xFFFFFFFFu, ms, o);
        __syncwarp();
        // q[h=warp][c]: c = lane&7, quarter = lane>>3 sums d in [16q, 16q+16)
        const int c = lane & 7, qr = lane >> 3;
        float acc = 0.f;
        #pragma unroll
        for (int dd = 0; dd < 16; ++dd) {
            int d = qr * 16 + dd;
            acc += sm[OFF_POOL + d] * __ldg(&Wq[d * 64 + warp * 8 + c]);
        }
        acc += __shfl_xor_sync(0xFFFFFFFFu, acc, 8);
        acc += __shfl_xor_sync(0xFFFFFFFFu, acc, 16);
        float qs = 0.35355339059327373f / (ms + 1e-10f);
        if (lane < 8) sm[OFF_QH + warp * 8 + lane] = acc * qs;
        __syncwarp();
        #pragma unroll
        for (int cc = 0; cc < 8; ++cc) qv[cc] = sm[OFF_QH + warp * 8 + cc];
    }

    // ---------- Phase 3: attention, warp = head (bias -1e9 kills masked rows) ----------
    {
        float sum = 0.f;
        float oa[8] = {0,0,0,0,0,0,0,0};
        #pragma unroll
        for (int i = 0; i < 16; ++i) {
            int r = i * 32 + lane;
            const uint32_t* kv = smu + OFF_KV + r * 9;
            float2 k0 = h2f2(kv[0]), k1 = h2f2(kv[1]), k2 = h2f2(kv[2]), k3 = h2f2(kv[3]);
            float bias = sm[OFF_KV + r * 9 + 8];
            float a = qv[0]*k0.x + qv[1]*k0.y + qv[2]*k1.x + qv[3]*k1.y
                    + qv[4]*k2.x + qv[5]*k2.y + qv[6]*k3.x + qv[7]*k3.y + bias;
            float p = __expf(a);
            sum += p;
            float2 v0 = h2f2(kv[4]), v1 = h2f2(kv[5]), v2 = h2f2(kv[6]), v3 = h2f2(kv[7]);
            oa[0] += p * v0.x; oa[1] += p * v0.y; oa[2] += p * v1.x; oa[3] += p * v1.y;
            oa[4] += p * v2.x; oa[5] += p * v2.y; oa[6] += p * v3.x; oa[7] += p * v3.y;
        }
        #pragma unroll
        for (int o = 16; o; o >>= 1) sum += __shfl_xor_sync(0xFFFFFFFFu, sum, o);
        #pragma unroll
        for (int c = 0; c < 8; ++c) {
            #pragma unroll
            for (int o = 16; o; o >>= 1) oa[c] += __shfl_xor_sync(0xFFFFFFFFu, oa[c], o);
        }
        if (lane == 0) {
            float inv = 1.f / sum;
            #pragma unroll
            for (int c = 0; c < 8; ++c) sm[OFF_OF + warp * 8 + c] = oa[c] * inv;
        }
    }
    __syncthreads();   // B3: OF ready for all warps

    // ---------- Phase 4: gate + output GEMM, h register-resident (acc -> A-frag identity) ----------
    // mt-half blocking: rows r0 + mh*32 .. +31.  Gate accumulator for nt=2k gives A-frag words
    // (a0,a1) of k-group k; nt=2k+1 gives (a2,a3).  No smem round trip for h.
    float* outs = out + (size_t)s * (RR * 64);
    #pragma unroll
    for (int mh = 0; mh < 2; ++mh) {
        // reload m A-frags for this half (gmem, L1/L2-hot)
        uint32_t Am[2][4][4];
        #pragma unroll
        for (int mt2 = 0; mt2 < 2; ++mt2)
            #pragma unroll
            for (int ktg = 0; ktg < 4; ++ktg) {
                const float* base = m_s + (r0 + (mh * 2 + mt2) * 16 + qrow) * 64 + ktg * 16 + 2 * qcol;
                float2 f0 = *(const float2*)base;
                float2 f1 = *(const float2*)(base + 8 * 64);
                float2 f2 = *(const float2*)(base + 8);
                float2 f3 = *(const float2*)(base + 8 * 64 + 8);
                Am[mt2][ktg][0] = packh2(f0.x, f0.y);
                Am[mt2][ktg][1] = packh2(f1.x, f1.y);
                Am[mt2][ktg][2] = packh2(f2.x, f2.y);
                Am[mt2][ktg][3] = packh2(f3.x, f3.y);
            }

        uint32_t Ah[2][4][4];
        // gate GEMM + sigmoid epilogue -> Ah
        #pragma unroll
        for (int kh = 0; kh < 4; ++kh) {
            #pragma unroll
            for (int sub = 0; sub < 2; ++sub) {
                const int nt = 2 * kh + sub;
                float cg[2][4] = {{0,0,0,0},{0,0,0,0}};
                #pragma unroll
                for (int ktg = 0; ktg < 4; ++ktg) {
                    uint32_t b0 = smu[OFF_WGF + ((nt * 4 + ktg) * 32 + lane) * 2];
                    uint32_t b1 = smu[OFF_WGF + ((nt * 4 + ktg) * 32 + lane) * 2 + 1];
                    #pragma unroll
                    for (int mt2 = 0; mt2 < 2; ++mt2)
                        mma_f16(cg[mt2], Am[mt2][ktg], b0, b1);
                }
                const int col0 = nt * 8 + 2 * qcol;
                float of0 = sm[OFF_OF + col0], of1 = sm[OFF_OF + col0 + 1];
                float bg0 = sm[OFF_BG + col0], bg1 = sm[OFF_BG + col0 + 1];
                #pragma unroll
                for (int mt2 = 0; mt2 < 2; ++mt2) {
                    float h0 = of0 / (1.f + __expf(-(cg[mt2][0] + bg0)));
                    float h1 = of1 / (1.f + __expf(-(cg[mt2][1] + bg1)));
                    float h2 = of0 / (1.f + __expf(-(cg[mt2][2] + bg0)));
                    float h3 = of1 / (1.f + __expf(-(cg[mt2][3] + bg1)));
                    Ah[mt2][kh][sub * 2]     = packh2(h0, h1);
                    Ah[mt2][kh][sub * 2 + 1] = packh2(h2, h3);
                }
            }
        }
        // output GEMM from Ah, store to gmem
        #pragma unroll
        for (int nt = 0; nt < 8; ++nt) {
            float co[2][4] = {{0,0,0,0},{0,0,0,0}};
            #pragma unroll
            for (int kh = 0; kh < 4; ++kh) {
                uint32_t b0 = smu[OFF_WOF + ((nt * 4 + kh) * 32 + lane) * 2];
                uint32_t b1 = smu[OFF_WOF + ((nt * 4 + kh) * 32 + lane) * 2 + 1];
                #pragma unroll
                for (int mt2 = 0; mt2 < 2; ++mt2)
                    mma_f16(co[mt2], Ah[mt2][kh], b0, b1);
            }
            const int col0 = nt * 8 + 2 * qcol;
            float bo0 = sm[OFF_BO + col0], bo1 = sm[OFF_BO + col0 + 1];
            #pragma unroll
            for (int mt2 = 0; mt2 < 2; ++mt2) {
                int row = r0 + (mh * 2 + mt2) * 16 + qrow;
                *(float2*)&outs[row * 64 + col0]       = make_float2(co[mt2][0] + bo0, co[mt2][1] + bo1);
                *(float2*)&outs[(row + 8) * 64 + col0] = make_float2(co[mt2][2] + bo0, co[mt2][3] + bo1);
            }
        }
    }
}

extern "C" void kernel_launch(void* const* d_in, const int* in_sizes, int n_in,
                              void* d_out, int out_size) {
    (void)in_sizes; (void)n_in; (void)out_size;
    const float* m    = (const float*)d_in[0];
    const float* mask = (const float*)d_in[1];
    const float* Wq   = (const float*)d_in[2];
    const float* Wk   = (const float*)d_in[3];
    const float* Wv   = (const float*)d_in[4];
    const float* Wg   = (const float*)d_in[5];
    const float* bg   = (const float*)d_in[6];
    const float* Wo   = (const float*)d_in[7];
    const float* bo   = (const float*)d_in[8];
    float* out = (float*)d_out;

    cudaFuncSetAttribute(ga_kernel, cudaFuncAttributeMaxDynamicSharedMemorySize, SMEM_BYTES);
    ga_kernel<<<SS, NT, SMEM_BYTES>>>(m, mask, Wq, Wk, Wv, Wg, bg, Wo, bo, out);
}